// round 1
// baseline (speedup 1.0000x reference)
#include <cuda_runtime.h>

// RoIAlign (TF crop_and_resize semantics): one block per RoI, one thread per channel.
// featuremap: (N=2, C=256, H=200, W=304) f32, rois: (M,5) [id,x1,y1,x2,y2], scale scalar.
// out: (M, 256, 7, 7) f32.

#define CROP 7
#define NPTS 49
#define C_CH 256
#define H_IM 200
#define W_IM 304

__global__ void __launch_bounds__(256, 4)
roialign_kernel(const float* __restrict__ img,
                const float* __restrict__ rois,
                const float* __restrict__ scale_p,
                float* __restrict__ out,
                int M)
{
    extern __shared__ float smem[];
    // layout: sout [256*49], then point arrays
    float* sout   = smem;                                // 12544 floats
    int*   s_tl   = (int*)(sout + C_CH * NPTS);          // 49
    int*   s_tr   = s_tl + NPTS;
    int*   s_bl   = s_tr + NPTS;
    int*   s_br   = s_bl + NPTS;
    float* s_ylp  = (float*)(s_br + NPTS);               // 49
    float* s_xlp  = s_ylp + NPTS;
    int*   s_val  = (int*)(s_xlp + NPTS);                // 49
    __shared__ int s_n;

    const int m   = blockIdx.x;
    const int tid = threadIdx.x;
    if (m >= M) return;

    const float scale = *scale_p;

    if (tid == 0) {
        s_n = (int)rois[(size_t)m * 5 + 0];
    }
    if (tid < NPTS) {
        const int i = tid / CROP;
        const int j = tid % CROP;
        const float x1 = rois[(size_t)m * 5 + 1] * scale;
        const float y1 = rois[(size_t)m * 5 + 2] * scale;
        const float x2 = rois[(size_t)m * 5 + 3] * scale;
        const float y2 = rois[(size_t)m * 5 + 4] * scale;
        const float sw = (x2 - x1) * (1.0f / CROP);
        const float sh = (y2 - y1) * (1.0f / CROP);
        // sample coordinate in feature space (bin center - 0.5)
        const float x = x1 + sw * 0.5f - 0.5f + (float)j * sw;
        const float y = y1 + sh * 0.5f - 0.5f + (float)i * sh;

        const bool vy = (y >= 0.0f) && (y <= (float)(H_IM - 1));
        const bool vx = (x >= 0.0f) && (x <= (float)(W_IM - 1));

        const float yf = floorf(y);
        const float xf = floorf(x);
        int yt = (int)yf;            int yb = (int)ceilf(y);
        int xl = (int)xf;            int xr = (int)ceilf(x);
        yt = min(max(yt, 0), H_IM - 1);
        yb = min(max(yb, 0), H_IM - 1);
        xl = min(max(xl, 0), W_IM - 1);
        xr = min(max(xr, 0), W_IM - 1);

        s_tl[tid] = yt * W_IM + xl;
        s_tr[tid] = yt * W_IM + xr;
        s_bl[tid] = yb * W_IM + xl;
        s_br[tid] = yb * W_IM + xr;
        s_ylp[tid] = y - yf;
        s_xlp[tid] = x - xf;
        s_val[tid] = (vx && vy) ? 1 : 0;
    }
    __syncthreads();

    const int c = tid;  // 256 threads == 256 channels
    const float* __restrict__ pc =
        img + ((size_t)s_n * C_CH + (size_t)c) * (size_t)(H_IM * W_IM);

    #pragma unroll 7
    for (int p = 0; p < NPTS; ++p) {
        float v = 0.0f;
        if (s_val[p]) {
            const float tl = __ldg(pc + s_tl[p]);
            const float tr = __ldg(pc + s_tr[p]);
            const float bl = __ldg(pc + s_bl[p]);
            const float br = __ldg(pc + s_br[p]);
            const float xlp = s_xlp[p];
            const float ylp = s_ylp[p];
            const float top = fmaf(tr - tl, xlp, tl);
            const float bot = fmaf(br - bl, xlp, bl);
            v = fmaf(bot - top, ylp, top);
        }
        sout[c * NPTS + p] = v;   // stride 49 (odd) -> bank-conflict-free
    }
    __syncthreads();

    // Coalesced float4 flush of the whole 256x49 tile.
    float4* __restrict__ o4 = (float4*)(out + (size_t)m * (C_CH * NPTS));
    const float4* __restrict__ s4 = (const float4*)sout;
    const int n4 = (C_CH * NPTS) / 4;  // 3136
    for (int idx = tid; idx < n4; idx += blockDim.x) {
        o4[idx] = s4[idx];
    }
}

extern "C" void kernel_launch(void* const* d_in, const int* in_sizes, int n_in,
                              void* d_out, int out_size)
{
    const float* img   = (const float*)d_in[0];
    const float* rois  = (const float*)d_in[1];
    const float* scale = (const float*)d_in[2];
    float* out = (float*)d_out;

    const int M = in_sizes[1] / 5;

    const int smem_bytes = (C_CH * NPTS) * 4   // sout
                         + NPTS * 4 * 4        // 4 int offset arrays
                         + NPTS * 4 * 2        // 2 float lerp arrays
                         + NPTS * 4;           // valid
    static int configured = -1;
    if (configured != smem_bytes) {
        cudaFuncSetAttribute(roialign_kernel,
                             cudaFuncAttributeMaxDynamicSharedMemorySize,
                             smem_bytes);
        configured = smem_bytes;
    }

    roialign_kernel<<<M, 256, smem_bytes>>>(img, rois, scale, out, M);
}

// round 2
// speedup vs baseline: 3.4164x; 3.4164x over previous
#include <cuda_runtime.h>

// RoIAlign (TF crop_and_resize semantics) via per-box patch staging.
// featuremap: (N=2, C=256, H=200, W=304) f32, rois: (M,5) [id,x1,y1,x2,y2], scale.
// out: (M, 256, 7, 7) f32.
//
// Geometry: box size <= 256 image px, scale = 1/16 -> sample grid spans <= 16
// feature pixels in each dim. So each (box, channel) needs only a 16x16 patch.
// Block = box. Warp = channel worker (8 warps x 32 channels each).
//  Phase 1: 49 threads compute sample points + patch-relative tap offsets.
//  Phase 2: each warp, per channel: coalesced 16x16 patch load -> SMEM,
//           lanes = points do 4 SMEM taps + bilerp, coalesced STG of 49 floats.

#define CROP 7
#define NPTS 49
#define C_CH 256
#define H_IM 200
#define W_IM 304
#define PSTRIDE 17            // padded patch row stride (bank-conflict relief)
#define PATCH_ELEMS (16 * PSTRIDE)

__global__ void __launch_bounds__(256, 6)
roialign_patch_kernel(const float* __restrict__ img,
                      const float* __restrict__ rois,
                      const float* __restrict__ scale_p,
                      float* __restrict__ out,
                      int M)
{
    __shared__ float s_patch[8 * PATCH_ELEMS];   // one 16x16(+pad) patch per warp
    __shared__ int   s_otl[NPTS], s_otr[NPTS], s_obl[NPTS], s_obr[NPTS];
    __shared__ float s_xlp[NPTS], s_ylp[NPTS];
    __shared__ int   s_val[NPTS];
    __shared__ int   s_n, s_ylo, s_xlo;

    const int m   = blockIdx.x;
    const int tid = threadIdx.x;
    if (m >= M) return;

    // ---------------- Phase 1: per-box sample points ----------------
    if (tid < NPTS) {
        const float scale = *scale_p;
        const float* roi = rois + (size_t)m * 5;
        const float x1s = roi[1] * scale;
        const float y1s = roi[2] * scale;
        const float x2s = roi[3] * scale;
        const float y2s = roi[4] * scale;
        const float sw = (x2s - x1s) * (1.0f / CROP);
        const float sh = (y2s - y1s) * (1.0f / CROP);
        const float xb = x1s + sw * 0.5f - 0.5f;   // sample x at j=0
        const float yb = y1s + sh * 0.5f - 0.5f;   // sample y at i=0

        const int i = tid / CROP;
        const int j = tid % CROP;
        const float x = xb + (float)j * sw;
        const float y = yb + (float)i * sh;

        const bool vy = (y >= 0.0f) && (y <= (float)(H_IM - 1));
        const bool vx = (x >= 0.0f) && (x <= (float)(W_IM - 1));

        const float yf = floorf(y);
        const float xf = floorf(x);
        int yt = min(max((int)yf, 0), H_IM - 1);
        int ybo = min(max((int)ceilf(y), 0), H_IM - 1);
        int xl = min(max((int)xf, 0), W_IM - 1);
        int xr = min(max((int)ceilf(x), 0), W_IM - 1);

        // Patch origin (monotone in i/j -> min is at i=0/j=0, clamped).
        const int ylo = min(max((int)floorf(yb), 0), H_IM - 1);
        const int xlo = min(max((int)floorf(xb), 0), W_IM - 1);
        if (tid == 0) {
            s_n   = (int)roi[0];
            s_ylo = ylo;
            s_xlo = xlo;
        }

        const int ry0 = min(yt - ylo, 15);
        const int ry1 = min(ybo - ylo, 15);
        const int cx0 = min(xl - xlo, 15);
        const int cx1 = min(xr - xlo, 15);

        s_otl[tid] = ry0 * PSTRIDE + cx0;
        s_otr[tid] = ry0 * PSTRIDE + cx1;
        s_obl[tid] = ry1 * PSTRIDE + cx0;
        s_obr[tid] = ry1 * PSTRIDE + cx1;
        s_ylp[tid] = y - yf;
        s_xlp[tid] = x - xf;
        s_val[tid] = (vx && vy) ? 1 : 0;
    }
    __syncthreads();

    // ---------------- Phase 2: per-warp channel loop ----------------
    const int wid  = tid >> 5;
    const int lane = tid & 31;
    float* patch = s_patch + wid * PATCH_ELEMS;

    const int ylo = s_ylo;
    const int xlo = s_xlo;
    const size_t img_base = (size_t)s_n * C_CH * (size_t)(H_IM * W_IM);
    float* __restrict__ out_m = out + (size_t)m * (C_CH * NPTS);

    for (int c = wid; c < C_CH; c += 8) {
        const float* __restrict__ pc = img + img_base + (size_t)c * (H_IM * W_IM);

        // Coalesced 16x16 patch load (clamped at image edges; over-read rows
        // are simply unused by the tap offsets).
        #pragma unroll
        for (int k = 0; k < 8; ++k) {
            const int e  = k * 32 + lane;
            const int r  = e >> 4;
            const int cc = e & 15;
            const int yy = min(ylo + r, H_IM - 1);
            const int xx = min(xlo + cc, W_IM - 1);
            patch[r * PSTRIDE + cc] = __ldg(pc + yy * W_IM + xx);
        }
        __syncwarp();

        float* __restrict__ op = out_m + c * NPTS;
        #pragma unroll
        for (int it = 0; it < 2; ++it) {
            const int p = it * 32 + lane;
            if (p < NPTS) {
                float v = 0.0f;
                if (s_val[p]) {
                    const float tl = patch[s_otl[p]];
                    const float tr = patch[s_otr[p]];
                    const float bl = patch[s_obl[p]];
                    const float br = patch[s_obr[p]];
                    const float xlp = s_xlp[p];
                    const float top = fmaf(tr - tl, xlp, tl);
                    const float bot = fmaf(br - bl, xlp, bl);
                    v = fmaf(bot - top, s_ylp[p], top);
                }
                op[p] = v;
            }
        }
        __syncwarp();   // all lanes done reading patch before next overwrite
    }
}

extern "C" void kernel_launch(void* const* d_in, const int* in_sizes, int n_in,
                              void* d_out, int out_size)
{
    const float* img   = (const float*)d_in[0];
    const float* rois  = (const float*)d_in[1];
    const float* scale = (const float*)d_in[2];
    float* out = (float*)d_out;

    const int M = in_sizes[1] / 5;
    roialign_patch_kernel<<<M, 256>>>(img, rois, scale, out, M);
}

// round 3
// speedup vs baseline: 5.2305x; 1.5310x over previous
#include <cuda_runtime.h>

// RoIAlign (TF crop_and_resize) — register-resident point params + float4 patch staging.
// featuremap: (N=2,C=256,H=200,W=304) f32; rois: (M,5) [id,x1,y1,x2,y2]; scale scalar.
// out: (M,256,7,7) f32.
//
// Block = box, warp = channel worker (8 warps, 32 channels each).
// Sample grid spans <= 15 feature px (box <= 256 img px, scale 1/16), so a fixed
// 16x20 patch with clamped origin covers all taps fully in-bounds:
//   ys = min(max(floor(y0),0), H-16), xs = min((max(floor(x0),0)) & ~3, W-20).
// Patch = 80 float4 -> 3 LDG.128 / 3 STS.128 per channel; taps via 8 LDS.32;
// next channel's patch prefetched into registers during compute.

#define CROP 7
#define NPTS 49
#define C_CH 256
#define H_IM 200
#define W_IM 304
#define PROWS 16
#define PCOLS 20
#define PF4   80            // 16*20/4 float4 per patch

__global__ void __launch_bounds__(256)
roialign3_kernel(const float* __restrict__ img,
                 const float* __restrict__ rois,
                 const float* __restrict__ scale_p,
                 float* __restrict__ out,
                 int M)
{
    __shared__ __align__(16) float s_patch[8 * PROWS * PCOLS];  // 10 KB

    const int m    = blockIdx.x;
    const int tid  = threadIdx.x;
    const int wid  = tid >> 5;
    const int lane = tid & 31;
    if (m >= M) return;

    // ---- per-thread (block-uniform) ROI params ----
    const float scale = *scale_p;
    const float* roi = rois + (size_t)m * 5;
    const int   n   = (int)roi[0];
    const float x1s = roi[1] * scale;
    const float y1s = roi[2] * scale;
    const float sw  = (roi[3] * scale - x1s) * (1.0f / CROP);
    const float sh  = (roi[4] * scale - y1s) * (1.0f / CROP);
    const float xb  = x1s + sw * 0.5f - 0.5f;
    const float yb  = y1s + sh * 0.5f - 0.5f;

    const int ylo = min(max((int)floorf(yb), 0), H_IM - 1);
    const int xlo = min(max((int)floorf(xb), 0), W_IM - 1);
    const int ys  = min(ylo, H_IM - PROWS);
    const int xs  = min(xlo & ~3, W_IM - PCOLS);

    // ---- per-lane point params (points p = lane and lane+32), registers ----
    int   off_tl[2], off_tr[2], off_bl[2], off_br[2];
    float xlp[2], ylp[2];
    bool  val[2];
    #pragma unroll
    for (int t = 0; t < 2; ++t) {
        const int p = lane + t * 32;
        const int pi = (p < NPTS) ? p : 0;
        const int i = pi / CROP;
        const int j = pi % CROP;
        const float x = xb + (float)j * sw;
        const float y = yb + (float)i * sh;
        const bool vy = (y >= 0.0f) && (y <= (float)(H_IM - 1));
        const bool vx = (x >= 0.0f) && (x <= (float)(W_IM - 1));
        const float yf = floorf(y);
        const float xf = floorf(x);
        const int yt = min(max((int)yf, 0), H_IM - 1) - ys;
        const int yB = min(max((int)ceilf(y), 0), H_IM - 1) - ys;
        const int xl = min(max((int)xf, 0), W_IM - 1) - xs;
        const int xr = min(max((int)ceilf(x), 0), W_IM - 1) - xs;
        off_tl[t] = yt * PCOLS + xl;
        off_tr[t] = yt * PCOLS + xr;
        off_bl[t] = yB * PCOLS + xl;
        off_br[t] = yB * PCOLS + xr;
        ylp[t] = y - yf;
        xlp[t] = x - xf;
        val[t] = vx && vy && (p < NPTS);
    }

    // ---- channel loop with register prefetch ----
    float* patch = s_patch + wid * (PROWS * PCOLS);
    const float* __restrict__ base =
        img + (size_t)n * C_CH * (size_t)(H_IM * W_IM) + (size_t)(ys * W_IM + xs);
    float* __restrict__ out_m = out + (size_t)m * (C_CH * NPTS);

    // float4 slots this lane loads: idx = t*32+lane (t=0..2), valid if < 80
    int   g_off[3];
    int   p_off[3];
    bool  g_ok[3];
    #pragma unroll
    for (int t = 0; t < 3; ++t) {
        const int idx = t * 32 + lane;
        const int r   = idx / 5;
        const int c4  = idx % 5;
        g_ok[t]  = (idx < PF4);
        g_off[t] = r * W_IM + c4 * 4;
        p_off[t] = r * PCOLS + c4 * 4;
    }

    const int plane = H_IM * W_IM;

    // prefetch first channel (c = wid)
    float4 buf[3];
    {
        const float* pc = base + (size_t)wid * plane;
        #pragma unroll
        for (int t = 0; t < 3; ++t)
            if (g_ok[t]) buf[t] = __ldg((const float4*)(pc + g_off[t]));
    }

    for (int c = wid; c < C_CH; c += 8) {
        // stage current patch
        #pragma unroll
        for (int t = 0; t < 3; ++t)
            if (g_ok[t]) *(float4*)(patch + p_off[t]) = buf[t];
        __syncwarp();

        // prefetch next channel while computing
        const int cn = c + 8;
        if (cn < C_CH) {
            const float* pc = base + (size_t)cn * plane;
            #pragma unroll
            for (int t = 0; t < 3; ++t)
                if (g_ok[t]) buf[t] = __ldg((const float4*)(pc + g_off[t]));
        }

        float* __restrict__ op = out_m + c * NPTS;
        #pragma unroll
        for (int t = 0; t < 2; ++t) {
            const int p = lane + t * 32;
            if (p < NPTS) {
                float v = 0.0f;
                if (val[t]) {
                    const float tl = patch[off_tl[t]];
                    const float tr = patch[off_tr[t]];
                    const float bl = patch[off_bl[t]];
                    const float br = patch[off_br[t]];
                    const float top = fmaf(tr - tl, xlp[t], tl);
                    const float bot = fmaf(br - bl, xlp[t], bl);
                    v = fmaf(bot - top, ylp[t], top);
                }
                op[p] = v;
            }
        }
        __syncwarp();   // finish reads before next STS overwrites patch
    }
}

extern "C" void kernel_launch(void* const* d_in, const int* in_sizes, int n_in,
                              void* d_out, int out_size)
{
    const float* img   = (const float*)d_in[0];
    const float* rois  = (const float*)d_in[1];
    const float* scale = (const float*)d_in[2];
    float* out = (float*)d_out;

    const int M = in_sizes[1] / 5;
    roialign3_kernel<<<M, 256>>>(img, rois, scale, out, M);
}

// round 5
// speedup vs baseline: 6.3760x; 1.2190x over previous
#include <cuda_runtime.h>
#include <cstdint>

// RoIAlign (TF crop_and_resize) — cp.async double-buffered patch staging,
// channel-slab grid for L2 locality.
// featuremap: (N=2,C=256,H=200,W=304) f32; rois: (M,5); out: (M,256,7,7) f32.
//
// grid = (M, 4): block handles box m, 64 channels [64*gy, 64*gy+64).
// warp = channel worker: 8 channels each (stride 8), per-channel 16-row patch
// (16 or 20 cols) staged via cp.async.cg into a double buffer.

#define CROP 7
#define NPTS 49
#define C_CH 256
#define H_IM 200
#define W_IM 304
#define PLANE (H_IM * W_IM)
#define PROWS 16
#define SSTRIDE 20                 // smem row stride (floats), 16B-chunk aligned
#define PATCH (PROWS * SSTRIDE)    // 320 floats
#define CH_PER_BLK 64
#define CH_PER_WARP 8

__device__ __forceinline__ void cp16(unsigned int dst, const float* src) {
    asm volatile("cp.async.cg.shared.global [%0], [%1], 16;\n"
                 :: "r"(dst), "l"(src));
}
__device__ __forceinline__ void cp_commit() {
    asm volatile("cp.async.commit_group;\n" ::: "memory");
}
template <int N>
__device__ __forceinline__ void cp_wait() {
    asm volatile("cp.async.wait_group %0;\n" :: "n"(N) : "memory");
}

struct TapParams {
    int   off_tl[2], off_tr[2], off_bl[2], off_br[2];
    float xlp[2], ylp[2];
    bool  val[2];
};

// NC4 = float4 chunks per patch row (4 = narrow, 5 = wide).
template <int NC4>
__device__ __forceinline__ void run_channels(
    const float* __restrict__ base,   // img plane origin + ys*W + xs (channel 0 of box's n)
    float* __restrict__ out_m,        // out + m*256*49
    float* __restrict__ sbuf,         // this warp's 2*PATCH floats
    unsigned int sbuf_sh,             // shared address of sbuf
    int c_first,                      // first channel for this warp
    int lane,
    const TapParams& tp)
{
    constexpr int NCHUNK = PROWS * NC4;   // 64 or 80

    // this lane's chunk slots
    int g_off[3], s_off[3];
    bool ok[3];
    #pragma unroll
    for (int t = 0; t < 3; ++t) {
        const int e = t * 32 + lane;
        ok[t] = (e < NCHUNK);
        const int r  = e / NC4;
        const int c4 = e % NC4;
        g_off[t] = r * W_IM + c4 * 4;
        s_off[t] = (r * SSTRIDE + c4 * 4) * 4;   // bytes
    }

    // prologue: issue channel 0 into buf 0
    {
        const float* pc = base + (size_t)c_first * PLANE;
        #pragma unroll
        for (int t = 0; t < 3; ++t)
            if (ok[t]) cp16(sbuf_sh + s_off[t], pc + g_off[t]);
        cp_commit();
    }

    #pragma unroll
    for (int k = 0; k < CH_PER_WARP; ++k) {
        const int c = c_first + k * 8;

        if (k + 1 < CH_PER_WARP) {
            // issue next channel into the other buffer (safe: its previous
            // readers finished at end of iteration k-1, fenced by __syncwarp)
            const float* pc = base + (size_t)(c + 8) * PLANE;
            const unsigned int db = sbuf_sh + (unsigned int)(((k + 1) & 1) * (PATCH * 4));
            #pragma unroll
            for (int t = 0; t < 3; ++t)
                if (ok[t]) cp16(db + s_off[t], pc + g_off[t]);
            cp_commit();
            cp_wait<1>();
        } else {
            cp_wait<0>();
        }
        __syncwarp();

        const float* patch = sbuf + (k & 1) * PATCH;
        float* __restrict__ op = out_m + (size_t)c * NPTS;
        #pragma unroll
        for (int t = 0; t < 2; ++t) {
            const int p = lane + t * 32;
            if (p < NPTS) {
                float v = 0.0f;
                if (tp.val[t]) {
                    const float tl = patch[tp.off_tl[t]];
                    const float tr = patch[tp.off_tr[t]];
                    const float bl = patch[tp.off_bl[t]];
                    const float br = patch[tp.off_br[t]];
                    const float top = fmaf(tr - tl, tp.xlp[t], tl);
                    const float bot = fmaf(br - bl, tp.xlp[t], bl);
                    v = fmaf(bot - top, tp.ylp[t], top);
                }
                op[p] = v;
            }
        }
        __syncwarp();
    }
}

__global__ void __launch_bounds__(256)
roialign4_kernel(const float* __restrict__ img,
                 const float* __restrict__ rois,
                 const float* __restrict__ scale_p,
                 float* __restrict__ out,
                 int M)
{
    __shared__ __align__(16) float s_patch[8 * 2 * PATCH];   // 20.5 KB

    const int m    = blockIdx.x;
    const int cg   = blockIdx.y;            // channel group (0..3)
    const int tid  = threadIdx.x;
    const int wid  = tid >> 5;
    const int lane = tid & 31;
    if (m >= M) return;

    // ---- block-uniform ROI params ----
    const float scale = *scale_p;
    const float* roi = rois + (size_t)m * 5;
    const int   n   = (int)roi[0];
    const float x1s = roi[1] * scale;
    const float y1s = roi[2] * scale;
    const float sw  = (roi[3] * scale - x1s) * (1.0f / CROP);
    const float sh  = (roi[4] * scale - y1s) * (1.0f / CROP);
    const float xb  = x1s + sw * 0.5f - 0.5f;
    const float yb  = y1s + sh * 0.5f - 0.5f;

    const int ylo = min(max((int)floorf(yb), 0), H_IM - 1);
    const int xlo = min(max((int)floorf(xb), 0), W_IM - 1);
    const int xhi = min(max((int)ceilf(xb + 6.0f * sw), 0), W_IM - 1);
    const int ys  = min(ylo, H_IM - PROWS);

    const int xs16 = min(xlo & ~3, W_IM - 16);
    const bool narrow = (xhi - xs16) <= 15;
    const int xs = narrow ? xs16 : min(xlo & ~3, W_IM - 20);

    // ---- per-lane tap params (points p = lane, lane+32) ----
    TapParams tp;
    #pragma unroll
    for (int t = 0; t < 2; ++t) {
        const int p = lane + t * 32;
        const int pi = (p < NPTS) ? p : 0;
        const int i = pi / CROP;
        const int j = pi % CROP;
        const float x = xb + (float)j * sw;
        const float y = yb + (float)i * sh;
        const bool vy = (y >= 0.0f) && (y <= (float)(H_IM - 1));
        const bool vx = (x >= 0.0f) && (x <= (float)(W_IM - 1));
        const float yf = floorf(y);
        const float xf = floorf(x);
        const int yt = min(max((int)yf, 0), H_IM - 1) - ys;
        const int yB = min(max((int)ceilf(y), 0), H_IM - 1) - ys;
        const int xl = min(max((int)xf, 0), W_IM - 1) - xs;
        const int xr = min(max((int)ceilf(x), 0), W_IM - 1) - xs;
        tp.off_tl[t] = yt * SSTRIDE + xl;
        tp.off_tr[t] = yt * SSTRIDE + xr;
        tp.off_bl[t] = yB * SSTRIDE + xl;
        tp.off_br[t] = yB * SSTRIDE + xr;
        tp.ylp[t] = y - yf;
        tp.xlp[t] = x - xf;
        tp.val[t] = vx && vy && (p < NPTS);
    }

    const float* __restrict__ base =
        img + (size_t)n * C_CH * (size_t)PLANE + (size_t)(ys * W_IM + xs);
    float* __restrict__ out_m = out + (size_t)m * (C_CH * NPTS);

    float* sbuf = s_patch + wid * (2 * PATCH);
    const unsigned int sbuf_sh = (unsigned int)__cvta_generic_to_shared(sbuf);
    const int c_first = cg * CH_PER_BLK + wid;

    if (narrow)
        run_channels<4>(base, out_m, sbuf, sbuf_sh, c_first, lane, tp);
    else
        run_channels<5>(base, out_m, sbuf, sbuf_sh, c_first, lane, tp);
}

extern "C" void kernel_launch(void* const* d_in, const int* in_sizes, int n_in,
                              void* d_out, int out_size)
{
    const float* img   = (const float*)d_in[0];
    const float* rois  = (const float*)d_in[1];
    const float* scale = (const float*)d_in[2];
    float* out = (float*)d_out;

    const int M = in_sizes[1] / 5;
    dim3 grid(M, C_CH / CH_PER_BLK);
    roialign4_kernel<<<grid, 256>>>(img, rois, scale, out, M);
}

// round 6
// speedup vs baseline: 9.0634x; 1.4215x over previous
#include <cuda_runtime.h>
#include <cstdint>

// RoIAlign (TF crop_and_resize) — cp.async double-buffered, demand-sized patches.
// featuremap: (N=2,C=256,H=200,W=304) f32; rois: (M,5); out: (M,256,7,7) f32.
//
// grid = (M, 4): block = (box m, 64-channel slab). warp = channel worker
// (8 channels, stride 8). Per channel, stage only the rows/cols the box's
// 7x7 bilinear taps actually need: nrows = yhi-ys+1 (<=16), cols in {8,16,20}.

#define CROP 7
#define NPTS 49
#define C_CH 256
#define H_IM 200
#define W_IM 304
#define PLANE (H_IM * W_IM)
#define SSTRIDE 20                 // smem row stride (floats), uniform for all paths
#define PATCH (16 * SSTRIDE)       // 320 floats
#define CH_PER_BLK 64
#define CH_PER_WARP 8

__device__ __forceinline__ void cp16(unsigned int dst, const float* src) {
    asm volatile("cp.async.cg.shared.global [%0], [%1], 16;\n"
                 :: "r"(dst), "l"(src));
}
__device__ __forceinline__ void cp_commit() {
    asm volatile("cp.async.commit_group;\n" ::: "memory");
}
template <int N>
__device__ __forceinline__ void cp_wait() {
    asm volatile("cp.async.wait_group %0;\n" :: "n"(N) : "memory");
}

struct TapParams {
    int   off_tl[2], off_tr[2], off_bl[2], off_br[2];
    float xlp[2], ylp[2];
    bool  val[2];
};

// NC4 = float4 chunks per patch row (2 / 4 / 5 -> 8 / 16 / 20 cols).
template <int NC4>
__device__ __forceinline__ void run_channels(
    const float* __restrict__ base,   // img + n*C*PLANE + ys*W + xs
    float* __restrict__ out_m,        // out + m*256*49
    float* __restrict__ sbuf,         // this warp's 2*PATCH floats
    unsigned int sbuf_sh,
    int c_first, int lane, int nchunk,
    const TapParams& tp)
{
    // this lane's chunk slots (<= 80 chunks total)
    int g_off[3], s_off[3];
    bool ok[3];
    #pragma unroll
    for (int t = 0; t < 3; ++t) {
        const int e = t * 32 + lane;
        ok[t] = (e < nchunk);
        const int r  = e / NC4;
        const int c4 = e % NC4;
        g_off[t] = r * W_IM + c4 * 4;
        s_off[t] = (r * SSTRIDE + c4 * 4) * 4;   // bytes
    }

    // prologue: channel 0 -> buf 0
    {
        const float* pc = base + (size_t)c_first * PLANE;
        #pragma unroll
        for (int t = 0; t < 3; ++t)
            if (ok[t]) cp16(sbuf_sh + s_off[t], pc + g_off[t]);
        cp_commit();
    }

    #pragma unroll
    for (int k = 0; k < CH_PER_WARP; ++k) {
        const int c = c_first + k * 8;

        if (k + 1 < CH_PER_WARP) {
            const float* pc = base + (size_t)(c + 8) * PLANE;
            const unsigned int db = sbuf_sh + (unsigned int)(((k + 1) & 1) * (PATCH * 4));
            #pragma unroll
            for (int t = 0; t < 3; ++t)
                if (ok[t]) cp16(db + s_off[t], pc + g_off[t]);
            cp_commit();
            cp_wait<1>();
        } else {
            cp_wait<0>();
        }
        __syncwarp();

        const float* patch = sbuf + (k & 1) * PATCH;
        float* __restrict__ op = out_m + (size_t)c * NPTS;
        #pragma unroll
        for (int t = 0; t < 2; ++t) {
            const int p = lane + t * 32;
            if (p < NPTS) {
                float v = 0.0f;
                if (tp.val[t]) {
                    const float tl = patch[tp.off_tl[t]];
                    const float tr = patch[tp.off_tr[t]];
                    const float bl = patch[tp.off_bl[t]];
                    const float br = patch[tp.off_br[t]];
                    const float top = fmaf(tr - tl, tp.xlp[t], tl);
                    const float bot = fmaf(br - bl, tp.xlp[t], bl);
                    v = fmaf(bot - top, tp.ylp[t], top);
                }
                op[p] = v;
            }
        }
        __syncwarp();
    }
}

__global__ void __launch_bounds__(256)
roialign5_kernel(const float* __restrict__ img,
                 const float* __restrict__ rois,
                 const float* __restrict__ scale_p,
                 float* __restrict__ out,
                 int M)
{
    __shared__ __align__(16) float s_patch[8 * 2 * PATCH];   // 20.5 KB

    const int m    = blockIdx.x;
    const int cg   = blockIdx.y;
    const int tid  = threadIdx.x;
    const int wid  = tid >> 5;
    const int lane = tid & 31;
    if (m >= M) return;

    // ---- block-uniform ROI params ----
    const float scale = *scale_p;
    const float* roi = rois + (size_t)m * 5;
    const int   n   = (int)roi[0];
    const float x1s = roi[1] * scale;
    const float y1s = roi[2] * scale;
    const float sw  = (roi[3] * scale - x1s) * (1.0f / CROP);
    const float sh  = (roi[4] * scale - y1s) * (1.0f / CROP);
    const float xb  = x1s + sw * 0.5f - 0.5f;
    const float yb  = y1s + sh * 0.5f - 0.5f;

    // y extent actually needed by the taps
    const int ylo = min(max((int)floorf(yb), 0), H_IM - 1);
    const int yhi = min(max((int)ceilf(yb + 6.0f * sh), 0), H_IM - 1);
    const int ys  = min(ylo, H_IM - 16 < 0 ? 0 : min(ylo, H_IM - 16));
    const int nrows = yhi - ys + 1;                       // <= 16

    // x extent and column-path selection
    const int xlo = min(max((int)floorf(xb), 0), W_IM - 1);
    const int xhi = min(max((int)ceilf(xb + 6.0f * sw), 0), W_IM - 1);
    const int xs8  = min(xlo & ~3, W_IM - 8);
    const int xs16 = min(xlo & ~3, W_IM - 16);
    const int path = ((xhi - xs8) <= 7) ? 0 : ((xhi - xs16) <= 15 ? 1 : 2);
    const int xs   = (path == 0) ? xs8 : (path == 1) ? xs16
                                       : min(xlo & ~3, W_IM - 20);

    // ---- per-lane tap params (points p = lane, lane+32) ----
    TapParams tp;
    #pragma unroll
    for (int t = 0; t < 2; ++t) {
        const int p = lane + t * 32;
        const int pi = (p < NPTS) ? p : 0;
        const int i = pi / CROP;
        const int j = pi % CROP;
        const float x = xb + (float)j * sw;
        const float y = yb + (float)i * sh;
        const bool vy = (y >= 0.0f) && (y <= (float)(H_IM - 1));
        const bool vx = (x >= 0.0f) && (x <= (float)(W_IM - 1));
        const float yf = floorf(y);
        const float xf = floorf(x);
        const int yt = min(max((int)yf, 0), H_IM - 1) - ys;
        const int yB = min(max((int)ceilf(y), 0), H_IM - 1) - ys;
        const int xl = min(max((int)xf, 0), W_IM - 1) - xs;
        const int xr = min(max((int)ceilf(x), 0), W_IM - 1) - xs;
        tp.off_tl[t] = yt * SSTRIDE + xl;
        tp.off_tr[t] = yt * SSTRIDE + xr;
        tp.off_bl[t] = yB * SSTRIDE + xl;
        tp.off_br[t] = yB * SSTRIDE + xr;
        tp.ylp[t] = y - yf;
        tp.xlp[t] = x - xf;
        tp.val[t] = vx && vy && (p < NPTS);
    }

    const float* __restrict__ base =
        img + (size_t)n * C_CH * (size_t)PLANE + (size_t)(ys * W_IM + xs);
    float* __restrict__ out_m = out + (size_t)m * (C_CH * NPTS);

    float* sbuf = s_patch + wid * (2 * PATCH);
    const unsigned int sbuf_sh = (unsigned int)__cvta_generic_to_shared(sbuf);
    const int c_first = cg * CH_PER_BLK + wid;

    if (path == 0)
        run_channels<2>(base, out_m, sbuf, sbuf_sh, c_first, lane, nrows * 2, tp);
    else if (path == 1)
        run_channels<4>(base, out_m, sbuf, sbuf_sh, c_first, lane, nrows * 4, tp);
    else
        run_channels<5>(base, out_m, sbuf, sbuf_sh, c_first, lane, nrows * 5, tp);
}

extern "C" void kernel_launch(void* const* d_in, const int* in_sizes, int n_in,
                              void* d_out, int out_size)
{
    const float* img   = (const float*)d_in[0];
    const float* rois  = (const float*)d_in[1];
    const float* scale = (const float*)d_in[2];
    float* out = (float*)d_out;

    const int M = in_sizes[1] / 5;
    dim3 grid(M, C_CH / CH_PER_BLK);
    roialign5_kernel<<<grid, 256>>>(img, rois, scale, out, M);
}